// round 1
// baseline (speedup 1.0000x reference)
#include <cuda_runtime.h>

#define Bn 2048
#define NB 2000
#define DB 30
#define KK 20
#define LL 40
#define PP 2

// Scratch (no allocations allowed in kernel_launch)
__device__ float d_wact[NB * LL];          // sigmoid((r - kappa))        [NB, L]
__device__ float d_gT[LL * Bn];            // g transposed                [L, B]
__device__ float d_partial[LL * KK * Bn];  // alpha-weighted per-(l,k)    [L, K, B]

// ---------------------------------------------------------------------------
// Kernel A: w_act[m,l] = sigmoid(r[l] - ||microbe_locs[m]-mu_bug[l]||^2)
// ---------------------------------------------------------------------------
__global__ void k_wact(const float* __restrict__ ml, const float* __restrict__ mu,
                       const float* __restrict__ r) {
    int idx = blockIdx.x * blockDim.x + threadIdx.x;
    if (idx >= NB * LL) return;
    int m = idx / LL, l = idx % LL;
    const float* a = ml + m * DB;
    const float* c = mu + l * DB;
    float s = 0.f;
#pragma unroll
    for (int d = 0; d < DB; d++) { float t = a[d] - c[d]; s = fmaf(t, t, s); }
    float z = r[l] - s;
    d_wact[idx] = 1.0f / (1.0f + __expf(-z));
}

// ---------------------------------------------------------------------------
// Kernel B: gT[l,b] = sum_m x[b,m] * w_act[m,l]
// Block: 16 b-rows x all 40 l-cols, blockDim = 320 (row = tid&15, colgrp = tid>>4)
// ---------------------------------------------------------------------------
#define CH 128
#define XS (CH + 5)   // pad so bank(row*XS+mm) = (5*row+mm)%32 -> conflict-free

__global__ __launch_bounds__(320) void k_gemm(const float* __restrict__ x) {
    __shared__ __align__(16) float xs[16 * XS];
    __shared__ __align__(16) float ws[CH * LL];
    int b0  = blockIdx.x * 16;
    int tid = threadIdx.x;
    int row = tid & 15;
    int cg  = tid >> 4;            // 0..19, 2 cols each
    float acc0 = 0.f, acc1 = 0.f;
    for (int m0 = 0; m0 < NB; m0 += CH) {
        for (int e = tid; e < 16 * CH; e += 320) {
            int rr = e >> 7, cc = e & (CH - 1);
            int m = m0 + cc;
            xs[rr * XS + cc] = (m < NB) ? x[(b0 + rr) * NB + m] : 0.f;
        }
        for (int e = tid; e < CH * LL; e += 320) {
            int m = m0 + e / LL;
            ws[e] = (m < NB) ? d_wact[m0 * LL + e] : 0.f;
        }
        __syncthreads();
#pragma unroll 4
        for (int mm = 0; mm < CH; mm++) {
            float  xv = xs[row * XS + mm];
            float2 w  = *(const float2*)&ws[mm * LL + 2 * cg];
            acc0 = fmaf(xv, w.x, acc0);
            acc1 = fmaf(xv, w.y, acc1);
        }
        __syncthreads();
    }
    d_gT[(2 * cg)     * Bn + b0 + row] = acc0;
    d_gT[(2 * cg + 1) * Bn + b0 + row] = acc1;
}

// ---------------------------------------------------------------------------
// Kernel C: NAM. One block per (k,l). Weights in smem (all LDS are lane-
// broadcast, conflict-free). Each thread runs the 1->16->16->8->1 MLP for
// its batch elements; FMA-pipe bound by design.
// partial[l,k,b] = sigmoid(alpha[l,k]) * sum_p F_{klp}(g[b,l])
// ---------------------------------------------------------------------------
__device__ __forceinline__ float elu(float z) {
    return z > 0.f ? z : (__expf(z) - 1.0f);
}

__global__ __launch_bounds__(256) void k_nam(
    const float* __restrict__ W1, const float* __restrict__ b1,
    const float* __restrict__ W2, const float* __restrict__ b2,
    const float* __restrict__ W3, const float* __restrict__ b3,
    const float* __restrict__ W4, const float* __restrict__ b4,
    const float* __restrict__ alpha) {
    __shared__ __align__(16) float sW1[PP][16], sB1[PP][16];
    __shared__ __align__(16) float sW2[PP][16][16], sB2[PP][16];  // sW2[p][j][i] = W2[klp,i,j]
    __shared__ __align__(16) float sW3[PP][8][16],  sB3[PP][8];   // sW3[p][j][i] = W3[klp,i,j]
    __shared__ __align__(16) float sW4[PP][8];
    __shared__ float sB4[PP];

    int k = blockIdx.x / LL, l = blockIdx.x % LL;
    int tid  = threadIdx.x;
    int base = (k * LL + l) * PP;       // flat klp index of p=0

    if (tid < 32) {
        int p = tid >> 4, i = tid & 15;
        sW1[p][i] = W1[base * 16 + tid];
        sB1[p][i] = b1[base * 16 + tid];
        sB2[p][i] = b2[base * 16 + tid];
    }
    for (int e = tid; e < PP * 256; e += 256) {   // W2: [p][i][j] -> sW2[p][j][i]
        int p = e >> 8, i = (e >> 4) & 15, j = e & 15;
        sW2[p][j][i] = W2[base * 256 + e];
    }
    if (tid < PP * 128) {                          // W3: [p][i(16)][j(8)] -> sW3[p][j][i]
        int e = tid;
        int p = e >> 7, i = (e >> 3) & 15, j = e & 7;
        sW3[p][j][i] = W3[base * 128 + e];
    }
    if (tid < 16) {
        int p = tid >> 3, j = tid & 7;
        sB3[p][j] = b3[base * 8 + tid];
        sW4[p][j] = W4[base * 8 + tid];
    }
    if (tid < 2) sB4[tid] = b4[base + tid];
    __syncthreads();

    float aAct = 1.0f / (1.0f + __expf(-alpha[l * KK + k]));
    float* outp = d_partial + (l * KK + k) * Bn;

    for (int b = tid; b < Bn; b += 256) {
        float g = d_gT[l * Bn + b];
        float s = 0.f;
        for (int p = 0; p < PP; p++) {
            float h1[16];
#pragma unroll
            for (int i = 0; i < 16; i++)
                h1[i] = elu(fmaf(g, sW1[p][i], sB1[p][i]));

            float h2[16];
#pragma unroll
            for (int j = 0; j < 16; j++) {
                const float4* w = (const float4*)sW2[p][j];
                float4 w0 = w[0], w1 = w[1], w2 = w[2], w3 = w[3];
                float a0 = fmaf(h1[0],  w0.x, sB2[p][j]);
                a0 = fmaf(h1[1],  w0.y, a0);
                a0 = fmaf(h1[2],  w0.z, a0);
                a0 = fmaf(h1[3],  w0.w, a0);
                float a1 = h1[4] * w1.x;
                a1 = fmaf(h1[5],  w1.y, a1);
                a1 = fmaf(h1[6],  w1.z, a1);
                a1 = fmaf(h1[7],  w1.w, a1);
                float a2 = h1[8] * w2.x;
                a2 = fmaf(h1[9],  w2.y, a2);
                a2 = fmaf(h1[10], w2.z, a2);
                a2 = fmaf(h1[11], w2.w, a2);
                float a3 = h1[12] * w3.x;
                a3 = fmaf(h1[13], w3.y, a3);
                a3 = fmaf(h1[14], w3.z, a3);
                a3 = fmaf(h1[15], w3.w, a3);
                h2[j] = elu((a0 + a1) + (a2 + a3));
            }

            float h3[8];
#pragma unroll
            for (int j = 0; j < 8; j++) {
                const float4* w = (const float4*)sW3[p][j];
                float4 w0 = w[0], w1 = w[1], w2 = w[2], w3 = w[3];
                float a0 = fmaf(h2[0],  w0.x, sB3[p][j]);
                a0 = fmaf(h2[1],  w0.y, a0);
                a0 = fmaf(h2[2],  w0.z, a0);
                a0 = fmaf(h2[3],  w0.w, a0);
                float a1 = h2[4] * w1.x;
                a1 = fmaf(h2[5],  w1.y, a1);
                a1 = fmaf(h2[6],  w1.z, a1);
                a1 = fmaf(h2[7],  w1.w, a1);
                float a2 = h2[8] * w2.x;
                a2 = fmaf(h2[9],  w2.y, a2);
                a2 = fmaf(h2[10], w2.z, a2);
                a2 = fmaf(h2[11], w2.w, a2);
                float a3 = h2[12] * w3.x;
                a3 = fmaf(h2[13], w3.y, a3);
                a3 = fmaf(h2[14], w3.z, a3);
                a3 = fmaf(h2[15], w3.w, a3);
                h3[j] = elu((a0 + a1) + (a2 + a3));
            }

            const float4* u = (const float4*)sW4[p];
            float4 u0 = u[0], u1 = u[1];
            float f = sB4[p];
            f = fmaf(h3[0], u0.x, f);
            f = fmaf(h3[1], u0.y, f);
            f = fmaf(h3[2], u0.z, f);
            f = fmaf(h3[3], u0.w, f);
            f = fmaf(h3[4], u1.x, f);
            f = fmaf(h3[5], u1.y, f);
            f = fmaf(h3[6], u1.z, f);
            f = fmaf(h3[7], u1.w, f);
            s += f;
        }
        outp[b] = aAct * s;
    }
}

// ---------------------------------------------------------------------------
// Kernel D: out[b,k] = beta[k] + sum_l partial[l,k,b]
// thread idx = k*2048 + b -> coalesced partial reads
// ---------------------------------------------------------------------------
__global__ void k_out(const float* __restrict__ beta, float* __restrict__ out) {
    int idx = blockIdx.x * blockDim.x + threadIdx.x;
    if (idx >= KK * Bn) return;
    int k = idx >> 11;       // /2048
    int b = idx & (Bn - 1);
    float s = beta[k];
#pragma unroll
    for (int l = 0; l < LL; l++) s += d_partial[(l * KK + k) * Bn + b];
    out[b * KK + k] = s;
}

// ---------------------------------------------------------------------------
extern "C" void kernel_launch(void* const* d_in, const int* in_sizes, int n_in,
                              void* d_out, int out_size) {
    const float* x     = (const float*)d_in[0];
    const float* ml    = (const float*)d_in[1];
    const float* mu    = (const float*)d_in[2];
    const float* r     = (const float*)d_in[3];
    const float* alpha = (const float*)d_in[4];
    const float* beta  = (const float*)d_in[5];
    const float* W1    = (const float*)d_in[6];
    const float* b1    = (const float*)d_in[7];
    const float* W2    = (const float*)d_in[8];
    const float* b2    = (const float*)d_in[9];
    const float* W3    = (const float*)d_in[10];
    const float* b3    = (const float*)d_in[11];
    const float* W4    = (const float*)d_in[12];
    const float* b4    = (const float*)d_in[13];
    float* out = (float*)d_out;

    k_wact<<<(NB * LL + 255) / 256, 256>>>(ml, mu, r);
    k_gemm<<<Bn / 16, 320>>>(x);
    k_nam<<<KK * LL, 256>>>(W1, b1, W2, b2, W3, b3, W4, b4, alpha);
    k_out<<<(KK * Bn + 255) / 256, 256>>>(beta, out);
}

// round 2
// speedup vs baseline: 1.0620x; 1.0620x over previous
#include <cuda_runtime.h>

#define Bn 2048
#define NB 2000
#define DB 30
#define KK 20
#define LL 40
#define PP 2

typedef unsigned long long u64;

// Scratch (no allocations allowed in kernel_launch)
__device__ float d_wact[NB * LL];          // sigmoid((r - kappa))        [NB, L]
__device__ float d_gT[LL * Bn];            // g transposed                [L, B]
__device__ float d_partial[LL * KK * Bn];  // alpha-weighted per-(l,k)    [L, K, B]

// ---------------- packed f32x2 helpers (FFMA2 only reachable via PTX) -------
__device__ __forceinline__ u64 pack2(float lo, float hi) {
    u64 r; asm("mov.b64 %0, {%1, %2};" : "=l"(r) : "f"(lo), "f"(hi)); return r;
}
__device__ __forceinline__ void unpack2(u64 v, float& lo, float& hi) {
    asm("mov.b64 {%0, %1}, %2;" : "=f"(lo), "=f"(hi) : "l"(v));
}
__device__ __forceinline__ u64 ffma2(u64 a, u64 b, u64 c) {
    u64 d; asm("fma.rn.f32x2 %0, %1, %2, %3;" : "=l"(d) : "l"(a), "l"(b), "l"(c)); return d;
}
__device__ __forceinline__ u64 fadd2(u64 a, u64 b) {
    u64 d; asm("add.rn.f32x2 %0, %1, %2;" : "=l"(d) : "l"(a), "l"(b)); return d;
}
__device__ __forceinline__ u64 fmul2(u64 a, u64 b) {
    u64 d; asm("mul.rn.f32x2 %0, %1, %2;" : "=l"(d) : "l"(a), "l"(b)); return d;
}
__device__ __forceinline__ float elu1(float z) {
    return z > 0.f ? z : (__expf(z) - 1.0f);
}
__device__ __forceinline__ u64 elu2(u64 z) {
    float lo, hi; unpack2(z, lo, hi);
    return pack2(elu1(lo), elu1(hi));
}

// ---------------------------------------------------------------------------
// Kernel A: w_act[m,l] = sigmoid(r[l] - ||microbe_locs[m]-mu_bug[l]||^2)
// ---------------------------------------------------------------------------
__global__ void k_wact(const float* __restrict__ ml, const float* __restrict__ mu,
                       const float* __restrict__ r) {
    int idx = blockIdx.x * blockDim.x + threadIdx.x;
    if (idx >= NB * LL) return;
    int m = idx / LL, l = idx % LL;
    const float* a = ml + m * DB;
    const float* c = mu + l * DB;
    float s = 0.f;
#pragma unroll
    for (int d = 0; d < DB; d++) { float t = a[d] - c[d]; s = fmaf(t, t, s); }
    float z = r[l] - s;
    d_wact[idx] = 1.0f / (1.0f + __expf(-z));
}

// ---------------------------------------------------------------------------
// Kernel B: gT[l,b] = sum_m x[b,m] * w_act[m,l]
// ---------------------------------------------------------------------------
#define CH 128
#define XS (CH + 5)

__global__ __launch_bounds__(320) void k_gemm(const float* __restrict__ x) {
    __shared__ __align__(16) float xs[16 * XS];
    __shared__ __align__(16) float ws[CH * LL];
    int b0  = blockIdx.x * 16;
    int tid = threadIdx.x;
    int row = tid & 15;
    int cg  = tid >> 4;            // 0..19, 2 cols each
    float acc0 = 0.f, acc1 = 0.f;
    for (int m0 = 0; m0 < NB; m0 += CH) {
        for (int e = tid; e < 16 * CH; e += 320) {
            int rr = e >> 7, cc = e & (CH - 1);
            int m = m0 + cc;
            xs[rr * XS + cc] = (m < NB) ? x[(b0 + rr) * NB + m] : 0.f;
        }
        for (int e = tid; e < CH * LL; e += 320) {
            int m = m0 + e / LL;
            ws[e] = (m < NB) ? d_wact[m0 * LL + e] : 0.f;
        }
        __syncthreads();
#pragma unroll 4
        for (int mm = 0; mm < CH; mm++) {
            float  xv = xs[row * XS + mm];
            float2 w  = *(const float2*)&ws[mm * LL + 2 * cg];
            acc0 = fmaf(xv, w.x, acc0);
            acc1 = fmaf(xv, w.y, acc1);
        }
        __syncthreads();
    }
    d_gT[(2 * cg)     * Bn + b0 + row] = acc0;
    d_gT[(2 * cg + 1) * Bn + b0 + row] = acc1;
}

// ---------------------------------------------------------------------------
// Kernel C: NAM, packed f32x2. One block per (k,l). Weights duplicated (w,w)
// into smem as u64; all LDS are lane-broadcast. Each thread handles 8 batch
// elements as 4 f32x2 pairs (2 per pass x 2 passes).
// partial[l,k,b] = sigmoid(alpha[l,k]) * sum_p F_{klp}(g[b,l])
// ---------------------------------------------------------------------------
__global__ __launch_bounds__(256) void k_nam(
    const float* __restrict__ W1, const float* __restrict__ b1,
    const float* __restrict__ W2, const float* __restrict__ b2,
    const float* __restrict__ W3, const float* __restrict__ b3,
    const float* __restrict__ W4, const float* __restrict__ b4,
    const float* __restrict__ alpha) {
    __shared__ __align__(16) u64 sW1d[PP][16], sB1d[PP][16], sB2d[PP][16];
    __shared__ __align__(16) u64 sW2d[PP][16][16];   // [p][j][i] = dup(W2[klp,i,j])
    __shared__ __align__(16) u64 sW3d[PP][8][16];    // [p][j][i] = dup(W3[klp,i,j])
    __shared__ __align__(16) u64 sB3d[PP][8], sW4d[PP][8];
    __shared__ __align__(16) u64 sB4d[PP];

    int k = blockIdx.x / LL, l = blockIdx.x % LL;
    int tid  = threadIdx.x;
    int base = (k * LL + l) * PP;       // flat klp index of p=0

    if (tid < 32) {
        int p = tid >> 4, i = tid & 15;
        float w = W1[base * 16 + tid];  sW1d[p][i] = pack2(w, w);
        float a = b1[base * 16 + tid];  sB1d[p][i] = pack2(a, a);
        float c = b2[base * 16 + tid];  sB2d[p][i] = pack2(c, c);
    }
#pragma unroll
    for (int e = tid; e < PP * 256; e += 256) {      // W2[p][i][j] -> sW2d[p][j][i]
        int p = e >> 8, i = (e >> 4) & 15, j = e & 15;
        float w = W2[base * 256 + e];
        sW2d[p][j][i] = pack2(w, w);
    }
    if (tid < PP * 128) {                            // W3[p][i(16)][j(8)] -> sW3d[p][j][i]
        int p = tid >> 7, i = (tid >> 3) & 15, j = tid & 7;
        float w = W3[base * 128 + tid];
        sW3d[p][j][i] = pack2(w, w);
    }
    if (tid < 16) {
        int p = tid >> 3, j = tid & 7;
        float a = b3[base * 8 + tid];  sB3d[p][j] = pack2(a, a);
        float w = W4[base * 8 + tid];  sW4d[p][j] = pack2(w, w);
    }
    if (tid < 2) { float a = b4[base + tid]; sB4d[tid] = pack2(a, a); }
    __syncthreads();

    float aAct = 1.0f / (1.0f + __expf(-alpha[l * KK + k]));
    u64 aAct2 = pack2(aAct, aAct);
    float* outp = d_partial + (l * KK + k) * Bn;
    const float* gp = d_gT + l * Bn;

#pragma unroll 1
    for (int u = 0; u < 2; u++) {
        int b0 = u * 1024 + 2 * tid;            // pair0 at b0, pair1 at b0+512
        float2 g0 = *(const float2*)&gp[b0];
        float2 g1 = *(const float2*)&gp[b0 + 512];
        u64 G0 = pack2(g0.x, g0.y);
        u64 G1 = pack2(g1.x, g1.y);
        u64 S0 = 0ull, S1 = 0ull;

#pragma unroll 1
        for (int p = 0; p < PP; p++) {
            u64 h1v[16][2];
#pragma unroll
            for (int i = 0; i < 16; i++) {
                u64 w = sW1d[p][i], bb = sB1d[p][i];
                h1v[i][0] = elu2(ffma2(G0, w, bb));
                h1v[i][1] = elu2(ffma2(G1, w, bb));
            }

            u64 h2v[16][2];
#pragma unroll
            for (int j = 0; j < 16; j++) {
                const ulonglong2* wr = (const ulonglong2*)sW2d[p][j];
                u64 bias = sB2d[p][j];
                u64 e0 = bias, o0 = 0ull, e1 = bias, o1 = 0ull;
#pragma unroll
                for (int q = 0; q < 8; q++) {
                    ulonglong2 w = wr[q];
                    e0 = ffma2(h1v[2 * q][0],     w.x, e0);
                    o0 = ffma2(h1v[2 * q + 1][0], w.y, o0);
                    e1 = ffma2(h1v[2 * q][1],     w.x, e1);
                    o1 = ffma2(h1v[2 * q + 1][1], w.y, o1);
                }
                h2v[j][0] = elu2(fadd2(e0, o0));
                h2v[j][1] = elu2(fadd2(e1, o1));
            }

            u64 h3v[8][2];
#pragma unroll
            for (int j = 0; j < 8; j++) {
                const ulonglong2* wr = (const ulonglong2*)sW3d[p][j];
                u64 bias = sB3d[p][j];
                u64 e0 = bias, o0 = 0ull, e1 = bias, o1 = 0ull;
#pragma unroll
                for (int q = 0; q < 8; q++) {
                    ulonglong2 w = wr[q];
                    e0 = ffma2(h2v[2 * q][0],     w.x, e0);
                    o0 = ffma2(h2v[2 * q + 1][0], w.y, o0);
                    e1 = ffma2(h2v[2 * q][1],     w.x, e1);
                    o1 = ffma2(h2v[2 * q + 1][1], w.y, o1);
                }
                h3v[j][0] = elu2(fadd2(e0, o0));
                h3v[j][1] = elu2(fadd2(e1, o1));
            }

            {
                const ulonglong2* wr = (const ulonglong2*)sW4d[p];
                u64 bias = sB4d[p];
                u64 e0 = bias, o0 = 0ull, e1 = bias, o1 = 0ull;
#pragma unroll
                for (int q = 0; q < 4; q++) {
                    ulonglong2 w = wr[q];
                    e0 = ffma2(h3v[2 * q][0],     w.x, e0);
                    o0 = ffma2(h3v[2 * q + 1][0], w.y, o0);
                    e1 = ffma2(h3v[2 * q][1],     w.x, e1);
                    o1 = ffma2(h3v[2 * q + 1][1], w.y, o1);
                }
                S0 = fadd2(S0, fadd2(e0, o0));
                S1 = fadd2(S1, fadd2(e1, o1));
            }
        }

        u64 r0 = fmul2(aAct2, S0);
        u64 r1 = fmul2(aAct2, S1);
        float lo, hi;
        unpack2(r0, lo, hi); *(float2*)&outp[b0]       = make_float2(lo, hi);
        unpack2(r1, lo, hi); *(float2*)&outp[b0 + 512] = make_float2(lo, hi);
    }
}

// ---------------------------------------------------------------------------
// Kernel D: out[b,k] = beta[k] + sum_l partial[l,k,b]
// ---------------------------------------------------------------------------
__global__ void k_out(const float* __restrict__ beta, float* __restrict__ out) {
    int idx = blockIdx.x * blockDim.x + threadIdx.x;
    if (idx >= KK * Bn) return;
    int k = idx >> 11;       // /2048
    int b = idx & (Bn - 1);
    float s = beta[k];
#pragma unroll
    for (int l = 0; l < LL; l++) s += d_partial[(l * KK + k) * Bn + b];
    out[b * KK + k] = s;
}

// ---------------------------------------------------------------------------
extern "C" void kernel_launch(void* const* d_in, const int* in_sizes, int n_in,
                              void* d_out, int out_size) {
    const float* x     = (const float*)d_in[0];
    const float* ml    = (const float*)d_in[1];
    const float* mu    = (const float*)d_in[2];
    const float* r     = (const float*)d_in[3];
    const float* alpha = (const float*)d_in[4];
    const float* beta  = (const float*)d_in[5];
    const float* W1    = (const float*)d_in[6];
    const float* b1    = (const float*)d_in[7];
    const float* W2    = (const float*)d_in[8];
    const float* b2    = (const float*)d_in[9];
    const float* W3    = (const float*)d_in[10];
    const float* b3    = (const float*)d_in[11];
    const float* W4    = (const float*)d_in[12];
    const float* b4    = (const float*)d_in[13];
    float* out = (float*)d_out;

    k_wact<<<(NB * LL + 255) / 256, 256>>>(ml, mu, r);
    k_gemm<<<Bn / 16, 320>>>(x);
    k_nam<<<KK * LL, 256>>>(W1, b1, W2, b2, W3, b3, W4, b4, alpha);
    k_out<<<(KK * Bn + 255) / 256, 256>>>(beta, out);
}